// round 7
// baseline (speedup 1.0000x reference)
#include <cuda_runtime.h>

// Shapes fixed by setup_inputs
#define RADIUS 3
constexpr int N_ = 2, C_ = 64, S_ = 4, H_ = 64, W_ = 44;
constexpr int P_  = H_ * W_;                // 2816
constexpr int SP_ = S_ * P_;                // 11264 (channel stride)

constexpr int TILE_Y  = 4;
constexpr int XTILE   = 22;                    // x-split: 2 CTAs per 44-col row band
constexpr int ROWS_SM = TILE_Y + 2 * RADIUS;   // 10
constexpr int WPAD    = 30;   // 15 ull/row (odd) -> conflict-free tap LDS.64 phases
constexpr int W0PAD   = 32;   // f0 pad: 8 float4/row -> conflict-free LDS.128
constexpr int NTHREADS = 448;                  // 14 warps: 7 tap rows x 2 ch halves
constexpr int NACT    = 7 * 32;                // exchange slots (lane-indexed)

constexpr int F1_ELEMS = C_ * ROWS_SM * WPAD;  // 19200 floats (76.8 KB)
constexpr int F0_ELEMS = C_ * TILE_Y * W0PAD;  // 8192 floats  (32.8 KB)
constexpr int SMEM_BYTES = (F1_ELEMS + F0_ELEMS) * (int)sizeof(float); // 109568

using ull = unsigned long long;

__device__ __forceinline__ ull pkdup(float a) {
    ull r; asm("mov.b64 %0, {%1, %1};" : "=l"(r) : "f"(a)); return r;
}
__device__ __forceinline__ void upk(float& lo, float& hi, ull v) {
    asm("mov.b64 {%0, %1}, %2;" : "=f"(lo), "=f"(hi) : "l"(v));
}
__device__ __forceinline__ void fma2(ull& d, ull a, ull b) {
    asm("fma.rn.f32x2 %0, %1, %2, %0;" : "+l"(d) : "l"(a), "l"(b));
}
__device__ __forceinline__ void add2(ull& d, ull a) {
    asm("add.rn.f32x2 %0, %0, %1;" : "+l"(d) : "l"(a));
}

__global__ __launch_bounds__(NTHREADS, 2)
void flow_kernel(const float* __restrict__ f0g, const float* __restrict__ f1g,
                 float* __restrict__ outg) {
    extern __shared__ float sm[];
    float* f1s = sm;                 // [C][ROWS_SM][WPAD], data cols 0..27 (gx x0-3..x0+24)
    float* f0s = sm + F1_ELEMS;      // [C][TILE_Y][W0PAD], data cols 0..21
    // aliases (dead-data reuse, guarded by syncs):
    float4* red4 = reinterpret_cast<float4*>(sm);                    // [7][96]
    ull*    exA  = reinterpret_cast<ull*>(sm + F1_ELEMS);            // [12][NACT]
    float4* exB  = reinterpret_cast<float4*>(sm + F1_ELEMS + 2 * 12 * NACT); // [NACT]

    const int tid  = threadIdx.x;
    const int wid  = tid >> 5;           // 0..13
    const int s    = tid & 31;
    const int h    = wid / 7;            // channel half
    const int g    = wid % 7;            // tap row, dy = g-3
    const int yl   = s >> 3;             // 0..3
    const int qx   = s & 7;              // quad index, active if < 6
    const bool active = (qx < 6);

    const int xh   = blockIdx.x;         // 0/1 x-half
    const int x0   = xh * XTILE;
    const int y0   = blockIdx.y * TILE_Y;
    const int b    = blockIdx.z;
    const int ni   = b >> 2;
    const int si   = b & 3;
    const int base1 = ((ni * C_) * S_ + si) * P_;

    // ================= zero tiles (halo + f0 pad stay 0) ====================
    {
        float4* z = reinterpret_cast<float4*>(sm);
        for (int i = tid; i < (F1_ELEMS + F0_ELEMS) / 4; i += NTHREADS)
            z[i] = make_float4(0.f, 0.f, 0.f, 0.f);
    }
    __syncthreads();

    // ================= stage f1: 28 cols x 10 rows x 64 ch ==================
    // unit = (ch, row); smem col j <-> gmem col x0-3+j
    for (int u = tid; u < C_ * ROWS_SM; u += NTHREADS) {
        const int ch  = u / ROWS_SM;
        const int row = u - ch * ROWS_SM;
        const int gy  = y0 - RADIUS + row;
        if ((unsigned)gy < (unsigned)H_) {
            const float* src = f1g + base1 + ch * SP_ + gy * W_;
            float* dst = f1s + (ch * ROWS_SM + row) * WPAD;
            #pragma unroll
            for (int j = 0; j < 28; ++j) {
                const int gx = x0 - RADIUS + j;
                if ((unsigned)gx < (unsigned)W_) dst[j] = src[gx];
            }
        }
    }
    // ================= stage f0: 22 cols x 4 rows x 64 ch ===================
    for (int u = tid; u < C_ * TILE_Y; u += NTHREADS) {
        const int ch  = u / TILE_Y;
        const int row = u - ch * TILE_Y;
        const float* src = f0g + base1 + ch * SP_ + (y0 + row) * W_ + x0;
        float* dst = f0s + (ch * TILE_Y + row) * W0PAD;
        #pragma unroll
        for (int j = 0; j < XTILE; ++j) dst[j] = src[j];
    }
    __syncthreads();

    // ====== main loop: 4 px x 7 taps x 32 ch, tap-paired f32x2 ==============
    ull   accP[12];
    float accS[4];
    #pragma unroll
    for (int i = 0; i < 12; ++i) accP[i] = 0ull;
    #pragma unroll
    for (int i = 0; i < 4; ++i) accS[i] = 0.0f;

    if (active) {
        const ull* __restrict__ tap =
            reinterpret_cast<const ull*>(f1s) +
            ((h * 32) * ROWS_SM + yl + g) * (WPAD / 2) + 2 * qx;
        const float4* __restrict__ a4 =
            reinterpret_cast<const float4*>(f0s) +
            ((h * 32) * TILE_Y + yl) * (W0PAD / 4) + qx;

        #pragma unroll 2
        for (int c = 0; c < 32; ++c) {
            const ull P0 = tap[0], P2 = tap[1], P4 = tap[2], P6 = tap[3], P8 = tap[4];
            const float4 A = a4[0];
            const ull aa0 = pkdup(A.x), aa1 = pkdup(A.y),
                      aa2 = pkdup(A.z), aa3 = pkdup(A.w);
            float t0lo, t0hi, t1lo, t1hi, t3lo, t3hi, t4lo, t4hi;
            upk(t0lo, t0hi, P0);
            upk(t1lo, t1hi, P2);
            upk(t3lo, t3hi, P6);
            upk(t4lo, t4hi, P8);

            fma2(accP[0],  aa0, P0);  fma2(accP[1],  aa0, P2);
            fma2(accP[2],  aa0, P4);
            fma2(accP[3],  aa1, P2);  fma2(accP[4],  aa1, P4);
            fma2(accP[5],  aa1, P6);
            fma2(accP[6],  aa2, P2);  fma2(accP[7],  aa2, P4);
            fma2(accP[8],  aa2, P6);
            fma2(accP[9],  aa3, P4);  fma2(accP[10], aa3, P6);
            fma2(accP[11], aa3, P8);
            accS[0] = fmaf(A.x, t3lo, accS[0]);
            accS[1] = fmaf(A.y, t0hi, accS[1]);
            accS[2] = fmaf(A.z, t4lo, accS[2]);
            accS[3] = fmaf(A.w, t1hi, accS[3]);

            tap += ROWS_SM * (WPAD / 2);
            a4  += TILE_Y * (W0PAD / 4);
        }
    }
    __syncthreads();   // all f1s/f0s reads done; aliases writable

    const int widx = g * 32 + s;
    if (active && h == 0) {
        #pragma unroll
        for (int j = 0; j < 12; ++j) exA[j * NACT + widx] = accP[j];
        exB[widx] = make_float4(accS[0], accS[1], accS[2], accS[3]);
    }
    __syncthreads();

    if (active && h == 1) {
        #pragma unroll
        for (int j = 0; j < 12; ++j) add2(accP[j], exA[j * NACT + widx]);
        const float4 eb = exB[widx];
        accS[0] += eb.x; accS[1] += eb.y; accS[2] += eb.z; accS[3] += eb.w;

        float acc[4][7];
        upk(acc[0][0], acc[0][1], accP[0]);
        upk(acc[0][2], acc[0][3], accP[1]);
        upk(acc[0][4], acc[0][5], accP[2]);  acc[0][6] = accS[0];
        acc[1][0] = accS[1];
        upk(acc[1][1], acc[1][2], accP[3]);
        upk(acc[1][3], acc[1][4], accP[4]);
        upk(acc[1][5], acc[1][6], accP[5]);
        upk(acc[2][0], acc[2][1], accP[6]);
        upk(acc[2][2], acc[2][3], accP[7]);
        upk(acc[2][4], acc[2][5], accP[8]);  acc[2][6] = accS[2];
        acc[3][0] = accS[3];
        upk(acc[3][1], acc[3][2], accP[9]);
        upk(acc[3][3], acc[3][4], accP[10]);
        upk(acc[3][5], acc[3][6], accP[11]);

        // masked per-row softmax stats (dy = g-3); masks use GLOBAL x
        const bool rowv = ((unsigned)(y0 + yl + g - RADIUS) < (unsigned)H_);
        const int xl0 = 4 * qx;
        #pragma unroll
        for (int p = 0; p < 4; ++p) {
            const int gx = x0 + xl0 + p;       // global x (px 22/23: junk, discarded)
            float m = -1e30f;
            #pragma unroll
            for (int d = 0; d < 7; ++d) {
                const bool v = rowv && ((unsigned)(gx + d - RADIUS) < (unsigned)W_);
                if (v) m = fmaxf(m, acc[p][d]);
            }
            float ss = 0.0f, fx = 0.0f;
            #pragma unroll
            for (int d = 0; d < 7; ++d) {
                const bool v = rowv && ((unsigned)(gx + d - RADIUS) < (unsigned)W_);
                const float e = v ? __expf((acc[p][d] - m) * 0.125f) : 0.0f;
                ss += e;
                fx += e * (float)(d - RADIUS);
            }
            red4[g * 96 + yl * 24 + xl0 + p] = make_float4(m, ss, fx, 0.0f);
        }
    }
    __syncthreads();

    // ================= combine 7 row-partials per pixel =====================
    if (tid < 96) {
        const int xl = tid % 24;
        const int yr = tid / 24;
        if (xl < XTILE) {
            float4 p[7];
            #pragma unroll
            for (int gg = 0; gg < 7; ++gg) p[gg] = red4[gg * 96 + yr * 24 + xl];

            float M = p[0].x;
            #pragma unroll
            for (int gg = 1; gg < 7; ++gg) M = fmaxf(M, p[gg].x);

            float S = 0.0f, FX = 0.0f, FY = 0.0f;
            #pragma unroll
            for (int gg = 0; gg < 7; ++gg) {
                const float wg = __expf((p[gg].x - M) * 0.125f);  // empty row -> 0
                S  += p[gg].y * wg;
                FX += p[gg].z * wg;
                FY += p[gg].y * wg * (float)(gg - RADIUS);
            }
            const float inv = 1.0f / S;
            const int ob = ((ni * 2) * S_ + si) * P_ + (y0 + yr) * W_ + x0 + xl;
            outg[ob]       = FX * inv;
            outg[ob + SP_] = FY * inv;
        }
    }
}

extern "C" void kernel_launch(void* const* d_in, const int* in_sizes, int n_in,
                              void* d_out, int out_size) {
    const float* f0 = (const float*)d_in[0];
    const float* f1 = (const float*)d_in[1];
    float* out = (float*)d_out;

    cudaFuncSetAttribute(flow_kernel,
                         cudaFuncAttributeMaxDynamicSharedMemorySize, SMEM_BYTES);

    dim3 grid(2, H_ / TILE_Y, N_ * S_);
    flow_kernel<<<grid, NTHREADS, SMEM_BYTES>>>(f0, f1, out);
}

// round 8
// speedup vs baseline: 2.0846x; 2.0846x over previous
#include <cuda_runtime.h>

// Shapes fixed by setup_inputs
#define RADIUS 3
constexpr int N_ = 2, C_ = 64, S_ = 4, H_ = 64, W_ = 44;
constexpr int P_  = H_ * W_;                // 2816
constexpr int SP_ = S_ * P_;                // 11264 (channel stride)

constexpr int TILE_Y  = 4;
constexpr int XTILE   = 22;                    // x-split: 2 CTAs per 44-col row band
constexpr int ROWS_SM = TILE_Y + 2 * RADIUS;   // 10
constexpr int WPAD    = 30;   // 15 ull/row (odd) -> conflict-free tap LDS.64 phases
constexpr int W0PAD   = 32;   // f0 pad: 8 float4/row -> conflict-free LDS.128
constexpr int NTHREADS = 448;                  // 14 warps: 7 tap rows x 2 ch halves
constexpr int NACT    = 7 * 32;                // exchange slots (lane-indexed)

constexpr int F1_ELEMS = C_ * ROWS_SM * WPAD;  // 19200 floats (76.8 KB)
constexpr int F0_ELEMS = C_ * TILE_Y * W0PAD;  // 8192 floats  (32.8 KB)
constexpr int SMEM_BYTES = (F1_ELEMS + F0_ELEMS) * (int)sizeof(float); // 109568

using ull = unsigned long long;

__device__ __forceinline__ ull pkdup(float a) {
    ull r; asm("mov.b64 %0, {%1, %1};" : "=l"(r) : "f"(a)); return r;
}
__device__ __forceinline__ void upk(float& lo, float& hi, ull v) {
    asm("mov.b64 {%0, %1}, %2;" : "=f"(lo), "=f"(hi) : "l"(v));
}
__device__ __forceinline__ void fma2(ull& d, ull a, ull b) {
    asm("fma.rn.f32x2 %0, %1, %2, %0;" : "+l"(d) : "l"(a), "l"(b));
}
__device__ __forceinline__ void add2(ull& d, ull a) {
    asm("add.rn.f32x2 %0, %0, %1;" : "+l"(d) : "l"(a));
}

__global__ __launch_bounds__(NTHREADS, 2)
void flow_kernel(const float* __restrict__ f0g, const float* __restrict__ f1g,
                 float* __restrict__ outg) {
    extern __shared__ float sm[];
    float* f1s = sm;                 // [C][ROWS_SM][WPAD], data cols 0..27 (gx = x0-3+j)
    float* f0s = sm + F1_ELEMS;      // [C][TILE_Y][W0PAD], data cols 0..21
    // aliases (dead-data reuse, guarded by syncs):
    float4* red4 = reinterpret_cast<float4*>(sm);                    // [7][96]
    ull*    exA  = reinterpret_cast<ull*>(sm + F1_ELEMS);            // [12][NACT]
    float4* exB  = reinterpret_cast<float4*>(sm + F1_ELEMS + 2 * 12 * NACT); // [NACT]

    const int tid  = threadIdx.x;
    const int wid  = tid >> 5;           // 0..13
    const int s    = tid & 31;
    const int h    = wid / 7;            // channel half
    const int g    = wid % 7;            // tap row, dy = g-3
    const int yl   = s >> 3;             // 0..3
    const int qx   = s & 7;              // quad index, active if < 6
    const bool active = (qx < 6);

    const int x0   = blockIdx.x * XTILE;
    const int y0   = blockIdx.y * TILE_Y;
    const int b    = blockIdx.z;
    const int ni   = b >> 2;
    const int si   = b & 3;
    const int base1 = ((ni * C_) * S_ + si) * P_;

    // ======= staging: thread = (row,col) slot, channel loop w/ MLP-8 ========
    // OOB slots write 0 for all channels -> halo zeroing is free.
    // f1 cols 28..29 and f0 cols 22..31 stay uninitialized: read only by the
    // two discarded junk pixels (xl 22,23), never by valid output.
    if (tid < 280) {                       // f1: 10 rows x 28 cols
        const int row = tid / 28;
        const int col = tid - row * 28;
        const int gy  = y0 - RADIUS + row;
        const int gx  = x0 - RADIUS + col;
        float* dst = f1s + row * WPAD + col;
        if ((unsigned)gy < (unsigned)H_ && (unsigned)gx < (unsigned)W_) {
            const float* src = f1g + base1 + gy * W_ + gx;
            #pragma unroll 8
            for (int ch = 0; ch < C_; ++ch)
                dst[ch * (ROWS_SM * WPAD)] = src[ch * SP_];
        } else {
            #pragma unroll 8
            for (int ch = 0; ch < C_; ++ch)
                dst[ch * (ROWS_SM * WPAD)] = 0.0f;
        }
    } else if (tid < 368) {                // f0: 4 rows x 22 cols
        const int t   = tid - 280;
        const int row = t / 22;
        const int col = t - row * 22;
        const float* src = f0g + base1 + (y0 + row) * W_ + x0 + col;
        float* dst = f0s + row * W0PAD + col;
        #pragma unroll 8
        for (int ch = 0; ch < C_; ++ch)
            dst[ch * (TILE_Y * W0PAD)] = src[ch * SP_];
    }
    __syncthreads();

    // ====== main loop: 4 px x 7 taps x 32 ch, tap-paired f32x2 ==============
    ull   accP[12];
    float accS[4];
    #pragma unroll
    for (int i = 0; i < 12; ++i) accP[i] = 0ull;
    #pragma unroll
    for (int i = 0; i < 4; ++i) accS[i] = 0.0f;

    if (active) {
        const ull* __restrict__ tap =
            reinterpret_cast<const ull*>(f1s) +
            ((h * 32) * ROWS_SM + yl + g) * (WPAD / 2) + 2 * qx;
        const float4* __restrict__ a4 =
            reinterpret_cast<const float4*>(f0s) +
            ((h * 32) * TILE_Y + yl) * (W0PAD / 4) + qx;

        #pragma unroll 2
        for (int c = 0; c < 32; ++c) {
            const ull P0 = tap[0], P2 = tap[1], P4 = tap[2], P6 = tap[3], P8 = tap[4];
            const float4 A = a4[0];
            const ull aa0 = pkdup(A.x), aa1 = pkdup(A.y),
                      aa2 = pkdup(A.z), aa3 = pkdup(A.w);
            float t0lo, t0hi, t1lo, t1hi, t3lo, t3hi, t4lo, t4hi;
            upk(t0lo, t0hi, P0);
            upk(t1lo, t1hi, P2);
            upk(t3lo, t3hi, P6);
            upk(t4lo, t4hi, P8);

            fma2(accP[0],  aa0, P0);  fma2(accP[1],  aa0, P2);
            fma2(accP[2],  aa0, P4);
            fma2(accP[3],  aa1, P2);  fma2(accP[4],  aa1, P4);
            fma2(accP[5],  aa1, P6);
            fma2(accP[6],  aa2, P2);  fma2(accP[7],  aa2, P4);
            fma2(accP[8],  aa2, P6);
            fma2(accP[9],  aa3, P4);  fma2(accP[10], aa3, P6);
            fma2(accP[11], aa3, P8);
            accS[0] = fmaf(A.x, t3lo, accS[0]);
            accS[1] = fmaf(A.y, t0hi, accS[1]);
            accS[2] = fmaf(A.z, t4lo, accS[2]);
            accS[3] = fmaf(A.w, t1hi, accS[3]);

            tap += ROWS_SM * (WPAD / 2);
            a4  += TILE_Y * (W0PAD / 4);
        }
    }
    __syncthreads();   // all f1s/f0s reads done; aliases writable

    const int widx = g * 32 + s;
    if (active && h == 0) {
        #pragma unroll
        for (int j = 0; j < 12; ++j) exA[j * NACT + widx] = accP[j];
        exB[widx] = make_float4(accS[0], accS[1], accS[2], accS[3]);
    }
    __syncthreads();

    if (active && h == 1) {
        #pragma unroll
        for (int j = 0; j < 12; ++j) add2(accP[j], exA[j * NACT + widx]);
        const float4 eb = exB[widx];
        accS[0] += eb.x; accS[1] += eb.y; accS[2] += eb.z; accS[3] += eb.w;

        float acc[4][7];
        upk(acc[0][0], acc[0][1], accP[0]);
        upk(acc[0][2], acc[0][3], accP[1]);
        upk(acc[0][4], acc[0][5], accP[2]);  acc[0][6] = accS[0];
        acc[1][0] = accS[1];
        upk(acc[1][1], acc[1][2], accP[3]);
        upk(acc[1][3], acc[1][4], accP[4]);
        upk(acc[1][5], acc[1][6], accP[5]);
        upk(acc[2][0], acc[2][1], accP[6]);
        upk(acc[2][2], acc[2][3], accP[7]);
        upk(acc[2][4], acc[2][5], accP[8]);  acc[2][6] = accS[2];
        acc[3][0] = accS[3];
        upk(acc[3][1], acc[3][2], accP[9]);
        upk(acc[3][3], acc[3][4], accP[10]);
        upk(acc[3][5], acc[3][6], accP[11]);

        // masked per-row softmax stats (dy = g-3); masks use GLOBAL x
        const bool rowv = ((unsigned)(y0 + yl + g - RADIUS) < (unsigned)H_);
        const int xl0 = 4 * qx;
        #pragma unroll
        for (int p = 0; p < 4; ++p) {
            const int gx = x0 + xl0 + p;     // xl 22,23: junk, discarded at combine
            float m = -1e30f;
            #pragma unroll
            for (int d = 0; d < 7; ++d) {
                const bool v = rowv && ((unsigned)(gx + d - RADIUS) < (unsigned)W_);
                if (v) m = fmaxf(m, acc[p][d]);
            }
            float ss = 0.0f, fx = 0.0f;
            #pragma unroll
            for (int d = 0; d < 7; ++d) {
                const bool v = rowv && ((unsigned)(gx + d - RADIUS) < (unsigned)W_);
                const float e = v ? __expf((acc[p][d] - m) * 0.125f) : 0.0f;
                ss += e;
                fx += e * (float)(d - RADIUS);
            }
            red4[g * 96 + yl * 24 + xl0 + p] = make_float4(m, ss, fx, 0.0f);
        }
    }
    __syncthreads();

    // ================= combine 7 row-partials per pixel =====================
    if (tid < 96) {
        const int xl = tid % 24;
        const int yr = tid / 24;
        if (xl < XTILE) {
            float4 p[7];
            #pragma unroll
            for (int gg = 0; gg < 7; ++gg) p[gg] = red4[gg * 96 + yr * 24 + xl];

            float M = p[0].x;
            #pragma unroll
            for (int gg = 1; gg < 7; ++gg) M = fmaxf(M, p[gg].x);

            float S = 0.0f, FX = 0.0f, FY = 0.0f;
            #pragma unroll
            for (int gg = 0; gg < 7; ++gg) {
                const float wg = __expf((p[gg].x - M) * 0.125f);  // empty row -> 0
                S  += p[gg].y * wg;
                FX += p[gg].z * wg;
                FY += p[gg].y * wg * (float)(gg - RADIUS);
            }
            const float inv = 1.0f / S;
            const int ob = ((ni * 2) * S_ + si) * P_ + (y0 + yr) * W_ + x0 + xl;
            outg[ob]       = FX * inv;
            outg[ob + SP_] = FY * inv;
        }
    }
}

extern "C" void kernel_launch(void* const* d_in, const int* in_sizes, int n_in,
                              void* d_out, int out_size) {
    const float* f0 = (const float*)d_in[0];
    const float* f1 = (const float*)d_in[1];
    float* out = (float*)d_out;

    cudaFuncSetAttribute(flow_kernel,
                         cudaFuncAttributeMaxDynamicSharedMemorySize, SMEM_BYTES);

    dim3 grid(W_ / XTILE, H_ / TILE_Y, N_ * S_);
    flow_kernel<<<grid, NTHREADS, SMEM_BYTES>>>(f0, f1, out);
}